// round 12
// baseline (speedup 1.0000x reference)
#include <cuda_runtime.h>

// labels[c] = argmax_q code_book[c][q]  (first-occurrence tie-break)
//   == reference argmin_q (tn[b,l,c] - cbn[c,q]): tn[b,l,c] is constant over
//   q, and cbn is a monotone strictly-increasing affine map of code_book, so
//   the GEMM, both LayerNorms, and the (B,L,C,Q) distance tensor are all dead
//   code. Output (B,L,C)=(4,512,256) f32: every row is labels[0..255].
//
// TERMINAL FORM (best sample 6.624us; config band 6.624-6.880 = replay floor
// +/- one 0.224us timer quantum): two kernels under Programmatic Dependent
// Launch, producer 32x256 (REDUX.MAX argmax, one warp per codebook row),
// consumer 512x256 (one STG.128 per thread). DRAM <1%, issue <5%; real data
// movement is 2.25 MB (~0.3us of an 8TB/s machine) — wall is fixed cost.

static constexpr int C    = 256;
static constexpr int Qdim = 256;

__device__ __align__(16) float g_labels_f[C];

// ---- Producer: one warp per codebook row (32 blocks x 8 warps) ----
__global__ void __launch_bounds__(256, 1)
argmax_kernel(const float* __restrict__ cb) {
    const int lane = threadIdx.x & 31;
    const int warp = threadIdx.x >> 5;
    const int row  = blockIdx.x * 8 + warp;

    const float4* __restrict__ rp =
        reinterpret_cast<const float4*>(cb + row * Qdim) + lane * 2;
    const float4 a = __ldg(rp);
    const float4 b = __ldg(rp + 1);

    // per-lane best over q = 8*lane .. 8*lane+7 (strict > keeps first index)
    float bv = a.x; int bi = 0;
    if (a.y > bv) { bv = a.y; bi = 1; }
    if (a.z > bv) { bv = a.z; bi = 2; }
    if (a.w > bv) { bv = a.w; bi = 3; }
    if (b.x > bv) { bv = b.x; bi = 4; }
    if (b.y > bv) { bv = b.y; bi = 5; }
    if (b.z > bv) { bv = b.z; bi = 6; }
    if (b.w > bv) { bv = b.w; bi = 7; }
    bi += lane * 8;

    // order-preserving bijection f32 -> u32, REDUX.MAX, lowest-lane tie-break
    const unsigned u    = __float_as_uint(bv);
    const unsigned skey = u ^ (unsigned)(((int)u >> 31) | 0x80000000);
    const unsigned m    = __reduce_max_sync(0xffffffffu, skey);
    const unsigned mask = __ballot_sync(0xffffffffu, skey == m);
    const int src       = __ffs(mask) - 1;     // lowest lane = lowest q range
    const int win       = __shfl_sync(0xffffffffu, bi, src);
    if (lane == 0) g_labels_f[row] = (float)win;

    cudaTriggerProgrammaticLaunchCompletion();
}

// ---- Consumer: 512 blocks x 256 threads, one STG.128 per thread ----
__global__ void __launch_bounds__(256, 8)
broadcast_kernel(float4* __restrict__ out, int n4) {
    const int idx = blockIdx.x * blockDim.x + threadIdx.x;  // pre-sync math
    const int src = idx & (C / 4 - 1);

    cudaGridDependencySynchronize();   // wait only for argmax_kernel's stores

    const float4* __restrict__ lab4 =
        reinterpret_cast<const float4*>(g_labels_f);
    if (idx < n4) out[idx] = lab4[src];
}

extern "C" void kernel_launch(void* const* d_in, const int* in_sizes, int n_in,
                              void* d_out, int out_size) {
    // Locate code_book by element count (65536); all four sizes are distinct.
    const float* code_book = nullptr;
    for (int i = 0; i < n_in; ++i) {
        if (in_sizes[i] == C * Qdim) { code_book = (const float*)d_in[i]; break; }
    }
    if (!code_book) code_book = (const float*)d_in[2];

    argmax_kernel<<<32, 256>>>(code_book);

    const int n4 = out_size / 4;   // 131072 float4
    cudaLaunchConfig_t cfg = {};
    cfg.gridDim  = dim3(512, 1, 1);
    cfg.blockDim = dim3(256, 1, 1);
    cudaLaunchAttribute attr[1];
    attr[0].id = cudaLaunchAttributeProgrammaticStreamSerialization;
    attr[0].val.programmaticStreamSerializationAllowed = 1;
    cfg.attrs    = attr;
    cfg.numAttrs = 1;
    cudaLaunchKernelEx(&cfg, broadcast_kernel,
                       reinterpret_cast<float4*>(d_out), n4);
}

// round 13
// speedup vs baseline: 1.0337x; 1.0337x over previous
#include <cuda_runtime.h>

// labels[c] = argmax_q code_book[c][q]  (first-occurrence tie-break)
//   == reference argmin_q (tn[b,l,c] - cbn[c,q]): tn[b,l,c] is constant over
//   q, and cbn is a monotone strictly-increasing affine map of code_book, so
//   the GEMM, both LayerNorms, and the (B,L,C,Q) distance tensor are all dead
//   code. Output (B,L,C)=(4,512,256) f32: every row is labels[0..255].
//
// TERMINAL FORM: plain two-kernel pipeline (the only config never measured
// worse than 6.656us; identical binaries sample a +/-0.224us timer band, so
// wall time is the graph-replay floor — DRAM <1%, issue <5%, real data
// movement 2.25 MB ~= 0.3us of an 8TB/s machine).
//   producer: 32x256, one warp per codebook row, REDUX.MAX argmax
//   consumer: 512x256, one STG.128 per thread broadcasting the label row

static constexpr int C    = 256;
static constexpr int Qdim = 256;

__device__ __align__(16) float g_labels_f[C];

// ---- Producer: one warp per codebook row (32 blocks x 8 warps) ----
__global__ void __launch_bounds__(256, 1)
argmax_kernel(const float* __restrict__ cb) {
    const int lane = threadIdx.x & 31;
    const int warp = threadIdx.x >> 5;
    const int row  = blockIdx.x * 8 + warp;

    const float4* __restrict__ rp =
        reinterpret_cast<const float4*>(cb + row * Qdim) + lane * 2;
    const float4 a = __ldg(rp);
    const float4 b = __ldg(rp + 1);

    // per-lane best over q = 8*lane .. 8*lane+7 (strict > keeps first index)
    float bv = a.x; int bi = 0;
    if (a.y > bv) { bv = a.y; bi = 1; }
    if (a.z > bv) { bv = a.z; bi = 2; }
    if (a.w > bv) { bv = a.w; bi = 3; }
    if (b.x > bv) { bv = b.x; bi = 4; }
    if (b.y > bv) { bv = b.y; bi = 5; }
    if (b.z > bv) { bv = b.z; bi = 6; }
    if (b.w > bv) { bv = b.w; bi = 7; }
    bi += lane * 8;

    // order-preserving bijection f32 -> u32, REDUX.MAX, lowest-lane tie-break
    // (lowest winning lane = lowest q range; within-lane strict > kept the
    // first index, so this reproduces jnp.argmin first-occurrence exactly)
    const unsigned u    = __float_as_uint(bv);
    const unsigned skey = u ^ (unsigned)(((int)u >> 31) | 0x80000000);
    const unsigned m    = __reduce_max_sync(0xffffffffu, skey);
    const unsigned mask = __ballot_sync(0xffffffffu, skey == m);
    const int src       = __ffs(mask) - 1;
    const int win       = __shfl_sync(0xffffffffu, bi, src);
    if (lane == 0) g_labels_f[row] = (float)win;
}

// ---- Consumer: 512 blocks x 256 threads, one STG.128 per thread ----
__global__ void __launch_bounds__(256, 8)
broadcast_kernel(float4* __restrict__ out, int n4) {
    const int idx = blockIdx.x * blockDim.x + threadIdx.x;
    const float4* __restrict__ lab4 =
        reinterpret_cast<const float4*>(g_labels_f);
    if (idx < n4) out[idx] = lab4[idx & (C / 4 - 1)];
}

extern "C" void kernel_launch(void* const* d_in, const int* in_sizes, int n_in,
                              void* d_out, int out_size) {
    // Locate code_book by element count (65536); all four sizes are distinct.
    const float* code_book = nullptr;
    for (int i = 0; i < n_in; ++i) {
        if (in_sizes[i] == C * Qdim) { code_book = (const float*)d_in[i]; break; }
    }
    if (!code_book) code_book = (const float*)d_in[2];

    argmax_kernel<<<32, 256>>>(code_book);

    const int n4 = out_size / 4;   // 131072 float4
    broadcast_kernel<<<512, 256>>>(reinterpret_cast<float4*>(d_out), n4);
}

// round 14
// speedup vs baseline: 1.0386x; 1.0048x over previous
#include <cuda_runtime.h>

// labels[c] = argmax_q code_book[c][q]  (first-occurrence tie-break)
//   == reference argmin_q (tn[b,l,c] - cbn[c,q]): tn[b,l,c] is constant over
//   q, and cbn is a monotone strictly-increasing affine map of code_book, so
//   the GEMM, both LayerNorms, and the (B,L,C,Q) distance tensor are all dead
//   code. Output (B,L,C)=(4,512,256) f32: every row is labels[0..255].
//
// TERMINAL FORM: plain two-kernel pipeline (the only config never measured
// worse than 6.656us; identical binaries sample a +/-0.224us timer band, so
// wall time is the graph-replay floor — DRAM <1%, issue <5%, real data
// movement 2.25 MB ~= 0.3us of an 8TB/s machine).
//   producer: 32x256, one warp per codebook row, REDUX.MAX argmax
//   consumer: 512x256, one STG.128 per thread broadcasting the label row

static constexpr int C    = 256;
static constexpr int Qdim = 256;

__device__ __align__(16) float g_labels_f[C];

// ---- Producer: one warp per codebook row (32 blocks x 8 warps) ----
__global__ void __launch_bounds__(256, 1)
argmax_kernel(const float* __restrict__ cb) {
    const int lane = threadIdx.x & 31;
    const int warp = threadIdx.x >> 5;
    const int row  = blockIdx.x * 8 + warp;

    const float4* __restrict__ rp =
        reinterpret_cast<const float4*>(cb + row * Qdim) + lane * 2;
    const float4 a = __ldg(rp);
    const float4 b = __ldg(rp + 1);

    // per-lane best over q = 8*lane .. 8*lane+7 (strict > keeps first index)
    float bv = a.x; int bi = 0;
    if (a.y > bv) { bv = a.y; bi = 1; }
    if (a.z > bv) { bv = a.z; bi = 2; }
    if (a.w > bv) { bv = a.w; bi = 3; }
    if (b.x > bv) { bv = b.x; bi = 4; }
    if (b.y > bv) { bv = b.y; bi = 5; }
    if (b.z > bv) { bv = b.z; bi = 6; }
    if (b.w > bv) { bv = b.w; bi = 7; }
    bi += lane * 8;

    // order-preserving bijection f32 -> u32, REDUX.MAX, lowest-lane tie-break
    // (lowest winning lane = lowest q range; within-lane strict > kept the
    // first index, so this reproduces jnp.argmin first-occurrence exactly)
    const unsigned u    = __float_as_uint(bv);
    const unsigned skey = u ^ (unsigned)(((int)u >> 31) | 0x80000000);
    const unsigned m    = __reduce_max_sync(0xffffffffu, skey);
    const unsigned mask = __ballot_sync(0xffffffffu, skey == m);
    const int src       = __ffs(mask) - 1;
    const int win       = __shfl_sync(0xffffffffu, bi, src);
    if (lane == 0) g_labels_f[row] = (float)win;
}

// ---- Consumer: 512 blocks x 256 threads, one STG.128 per thread ----
__global__ void __launch_bounds__(256, 8)
broadcast_kernel(float4* __restrict__ out, int n4) {
    const int idx = blockIdx.x * blockDim.x + threadIdx.x;
    const float4* __restrict__ lab4 =
        reinterpret_cast<const float4*>(g_labels_f);
    if (idx < n4) out[idx] = lab4[idx & (C / 4 - 1)];
}

extern "C" void kernel_launch(void* const* d_in, const int* in_sizes, int n_in,
                              void* d_out, int out_size) {
    // Locate code_book by element count (65536); all four sizes are distinct.
    const float* code_book = nullptr;
    for (int i = 0; i < n_in; ++i) {
        if (in_sizes[i] == C * Qdim) { code_book = (const float*)d_in[i]; break; }
    }
    if (!code_book) code_book = (const float*)d_in[2];

    argmax_kernel<<<32, 256>>>(code_book);

    const int n4 = out_size / 4;   // 131072 float4
    broadcast_kernel<<<512, 256>>>(reinterpret_cast<float4*>(d_out), n4);
}